// round 15
// baseline (speedup 1.0000x reference)
#include <cuda_runtime.h>
#include <cuda_fp16.h>
#include <cstdint>

#define IN_F     4096
#define OUT_F    4096
#define N_TOK    8192
#define GROUP    128
#define NGROUPS  (IN_F / GROUP)
#define N_STAGES 4
#define QMAXF    15.0f

// ---------------- scratch (device globals; no runtime allocation) ----------
__device__ __half g_w_h[(size_t)OUT_F * IN_F];
__device__ __half g_x_h[(size_t)N_TOK * IN_F];

// ---------------------------------------------------------------------------
// Kernel 1: fused weight transform + x->fp16 conversion.
// Transposed float4 tile wT4[channel][row_quad]: 128 rows/block as 32 quads.
// Rotation LDS.128 lane-consecutive -> conflict-free; per-element instruction
// count halved vs R14. Dynamic smem (~73KB), 2 CTAs/SM.
// ---------------------------------------------------------------------------
#define ROWS_PB 128
#define NQUADS  (ROWS_PB / 4)                  // 32 row-quads
#define RPAD    33
#define TBLOCKS (NGROUPS * (OUT_F / ROWS_PB))  // 1024
#define XCHUNK  ((size_t)N_TOK * IN_F / TBLOCKS)  // 32768 elems / block

// dynamic smem layout (bytes)
#define OFF_WT4   0
#define SZ_WT4    (GROUP * RPAD * 16)          // 67584
#define OFF_CSC   (OFF_WT4 + SZ_WT4)
#define OFF_CC    (OFF_CSC + GROUP * 4)
#define OFF_SS    (OFF_CC + N_STAGES * 64 * 4)
#define OFF_PI    (OFF_SS + N_STAGES * 64 * 4)
#define OFF_PJ    (OFF_PI + N_STAGES * 64 * 4)
#define OFF_QS    (OFF_PJ + N_STAGES * 64 * 4)
#define OFF_QZ    (OFF_QS + ROWS_PB * 4)
#define TSMEM_SZ  (OFF_QZ + ROWS_PB * 4)       // ~73.5KB

__global__ __launch_bounds__(256) void transform_kernel(
    const float* __restrict__ weight,
    const float* __restrict__ channel_scales,
    const float* __restrict__ theta,
    const float* __restrict__ q_scale,
    const float* __restrict__ q_zp,
    const int*   __restrict__ pairs,
    const float* __restrict__ x)
{
    extern __shared__ char tsmem[];
    float4* wT4 = reinterpret_cast<float4*>(tsmem + OFF_WT4);  // [128][33]
    float*  csc = reinterpret_cast<float*>(tsmem + OFF_CSC);
    float*  cc  = reinterpret_cast<float*>(tsmem + OFF_CC);    // [4][64]
    float*  ss  = reinterpret_cast<float*>(tsmem + OFF_SS);
    int*    pi  = reinterpret_cast<int*>(tsmem + OFF_PI);
    int*    pj  = reinterpret_cast<int*>(tsmem + OFF_PJ);
    float*  qs  = reinterpret_cast<float*>(tsmem + OFF_QS);
    float*  qz  = reinterpret_cast<float*>(tsmem + OFF_QZ);

    const int g    = blockIdx.x;               // 0..31
    const int row0 = blockIdx.y * ROWS_PB;     // 0..3968
    const int tid  = threadIdx.x;
    const int wrp  = tid >> 5;                 // 0..7
    const int lane = tid & 31;

    // ---- fused x -> fp16 conversion (independent DRAM stream) ----
    {
        const int blk = blockIdx.y * NGROUPS + blockIdx.x;   // 0..1023
        const float* xs = x + (size_t)blk * XCHUNK;
        __half* xd = g_x_h + (size_t)blk * XCHUNK;
        #pragma unroll
        for (int t = 0; t < (int)(XCHUNK / (256 * 8)); t++) {  // 16 iters
            size_t i = ((size_t)(t * 256 + tid)) * 8;
            float4 v0 = *reinterpret_cast<const float4*>(xs + i);
            float4 v1 = *reinterpret_cast<const float4*>(xs + i + 4);
            __half2 h[4];
            h[0] = __floats2half2_rn(v0.x, v0.y);
            h[1] = __floats2half2_rn(v0.z, v0.w);
            h[2] = __floats2half2_rn(v1.x, v1.y);
            h[3] = __floats2half2_rn(v1.z, v1.w);
            *reinterpret_cast<uint4*>(xd + i) =
                *reinterpret_cast<const uint4*>(h);
        }
    }

    // ---- tables ----
    if (tid < GROUP) csc[tid] = channel_scales[g * GROUP + tid];
    {
        int st = tid >> 6, p = tid & 63;       // 256 = 4 stages x 64 pairs
        float s, c;
        sincosf(theta[st * (IN_F / 2) + g * 64 + p], &s, &c);
        cc[st * 64 + p] = c;
        ss[st * 64 + p] = s;
        pi[st * 64 + p] = pairs[st * IN_F + g * GROUP + 2 * p];
        pj[st * 64 + p] = pairs[st * IN_F + g * GROUP + 2 * p + 1];
    }
    if (tid < ROWS_PB) {
        int gi = (row0 + tid) * NGROUPS + g;
        qs[tid] = fminf(fmaxf(q_scale[gi], 1e-5f), 1e5f);
        qz[tid] = fminf(fmaxf(-rintf(q_zp[gi]), 0.0f), QMAXF);
    }
    __syncthreads();

    // ---- transposed load + channel scale (four rows per float4) ----
    const int lq = wrp * 4 + (lane >> 3);      // row-quad index 0..31
    const int rowa = row0 + 4 * lq;
    #pragma unroll
    for (int it = 0; it < 4; it++) {
        int c4 = ((lane & 7) + it * 8) * 4;
        float4 va = *reinterpret_cast<const float4*>(
            weight + (size_t)(rowa + 0) * IN_F + g * GROUP + c4);
        float4 vb = *reinterpret_cast<const float4*>(
            weight + (size_t)(rowa + 1) * IN_F + g * GROUP + c4);
        float4 vc = *reinterpret_cast<const float4*>(
            weight + (size_t)(rowa + 2) * IN_F + g * GROUP + c4);
        float4 vd = *reinterpret_cast<const float4*>(
            weight + (size_t)(rowa + 3) * IN_F + g * GROUP + c4);
        float s0 = csc[c4 + 0], s1 = csc[c4 + 1];
        float s2 = csc[c4 + 2], s3 = csc[c4 + 3];
        wT4[(c4 + 0) * RPAD + lq] =
            make_float4(va.x * s0, vb.x * s0, vc.x * s0, vd.x * s0);
        wT4[(c4 + 1) * RPAD + lq] =
            make_float4(va.y * s1, vb.y * s1, vc.y * s1, vd.y * s1);
        wT4[(c4 + 2) * RPAD + lq] =
            make_float4(va.z * s2, vb.z * s2, vc.z * s2, vd.z * s2);
        wT4[(c4 + 3) * RPAD + lq] =
            make_float4(va.w * s3, vb.w * s3, vc.w * s3, vd.w * s3);
    }
    __syncthreads();

    // ---- forward rotations: lane = row-quad, conflict-free LDS.128 ----
    #pragma unroll
    for (int st = 0; st < N_STAGES; st++) {
        #pragma unroll
        for (int t = 0; t < 8; t++) {
            int p = wrp + t * 8;
            float c = cc[st * 64 + p], s = ss[st * 64 + p];
            int i = pi[st * 64 + p], j = pj[st * 64 + p];
            float4 xi = wT4[i * RPAD + lane];
            float4 xj = wT4[j * RPAD + lane];
            wT4[i * RPAD + lane] = make_float4(
                 xi.x * c + xj.x * s,  xi.y * c + xj.y * s,
                 xi.z * c + xj.z * s,  xi.w * c + xj.w * s);
            wT4[j * RPAD + lane] = make_float4(
                -xi.x * s + xj.x * c, -xi.y * s + xj.y * c,
                -xi.z * s + xj.z * c, -xi.w * s + xj.w * c);
        }
        __syncthreads();
    }

    // ---- quant-dequant: lane owns rows 4*lane .. 4*lane+3 ----
    {
        float sa = qs[4 * lane + 0], za = qz[4 * lane + 0];
        float sb = qs[4 * lane + 1], zb = qz[4 * lane + 1];
        float sc = qs[4 * lane + 2], zc = qz[4 * lane + 2];
        float sd = qs[4 * lane + 3], zd = qz[4 * lane + 3];
        #pragma unroll
        for (int t = 0; t < 16; t++) {
            int c = wrp + t * 8;
            float4 v = wT4[c * RPAD + lane];
            float qa = fminf(fmaxf(rintf(v.x / sa) + za, 0.0f), QMAXF);
            float qb = fminf(fmaxf(rintf(v.y / sb) + zb, 0.0f), QMAXF);
            float qc = fminf(fmaxf(rintf(v.z / sc) + zc, 0.0f), QMAXF);
            float qd = fminf(fmaxf(rintf(v.w / sd) + zd, 0.0f), QMAXF);
            wT4[c * RPAD + lane] = make_float4(
                (qa - za) * sa, (qb - zb) * sb,
                (qc - zc) * sc, (qd - zd) * sd);
        }
    }
    __syncthreads();

    // ---- inverse rotations ----
    #pragma unroll
    for (int st = N_STAGES - 1; st >= 0; st--) {
        #pragma unroll
        for (int t = 0; t < 8; t++) {
            int p = wrp + t * 8;
            float c = cc[st * 64 + p], s = ss[st * 64 + p];
            int i = pi[st * 64 + p], j = pj[st * 64 + p];
            float4 xi = wT4[i * RPAD + lane];
            float4 xj = wT4[j * RPAD + lane];
            wT4[i * RPAD + lane] = make_float4(
                xi.x * c - xj.x * s, xi.y * c - xj.y * s,
                xi.z * c - xj.z * s, xi.w * c - xj.w * s);
            wT4[j * RPAD + lane] = make_float4(
                xi.x * s + xj.x * c, xi.y * s + xj.y * c,
                xi.z * s + xj.z * c, xi.w * s + xj.w * c);
        }
        __syncthreads();
    }

    // ---- unscale + fp16 store (8B stores, all four rows) ----
    #pragma unroll
    for (int it = 0; it < 4; it++) {
        int c4 = ((lane & 7) + it * 8) * 4;
        float4 u0 = wT4[(c4 + 0) * RPAD + lq];
        float4 u1 = wT4[(c4 + 1) * RPAD + lq];
        float4 u2 = wT4[(c4 + 2) * RPAD + lq];
        float4 u3 = wT4[(c4 + 3) * RPAD + lq];
        float i0 = csc[c4 + 0], i1 = csc[c4 + 1];
        float i2 = csc[c4 + 2], i3 = csc[c4 + 3];
        __half2 h[2];
        h[0] = __floats2half2_rn(u0.x / i0, u1.x / i1);
        h[1] = __floats2half2_rn(u2.x / i2, u3.x / i3);
        *reinterpret_cast<uint2*>(
            g_w_h + (size_t)(rowa + 0) * IN_F + g * GROUP + c4) =
            *reinterpret_cast<const uint2*>(h);
        h[0] = __floats2half2_rn(u0.y / i0, u1.y / i1);
        h[1] = __floats2half2_rn(u2.y / i2, u3.y / i3);
        *reinterpret_cast<uint2*>(
            g_w_h + (size_t)(rowa + 1) * IN_F + g * GROUP + c4) =
            *reinterpret_cast<const uint2*>(h);
        h[0] = __floats2half2_rn(u0.z / i0, u1.z / i1);
        h[1] = __floats2half2_rn(u2.z / i2, u3.z / i3);
        *reinterpret_cast<uint2*>(
            g_w_h + (size_t)(rowa + 2) * IN_F + g * GROUP + c4) =
            *reinterpret_cast<const uint2*>(h);
        h[0] = __floats2half2_rn(u0.w / i0, u1.w / i1);
        h[1] = __floats2half2_rn(u2.w / i2, u3.w / i3);
        *reinterpret_cast<uint2*>(
            g_w_h + (size_t)(rowa + 3) * IN_F + g * GROUP + c4) =
            *reinterpret_cast<const uint2*>(h);
    }
}

// ---------------------------------------------------------------------------
// Kernel 2: PERSISTENT fp16 mma.sync GEMM (measured ~615-620us; parked).
// ---------------------------------------------------------------------------
#define BM 128
#define BN 256
#define BK 128
#define NTHREADS 512
#define GRID_P   148
#define NTILES   ((OUT_F / BN) * (N_TOK / BM))            // 1024
#define ITERS_PT (IN_F / BK)                              // 32
#define A_STAGE_BYTES (BM * BK * 2)                       // 32768
#define B_STAGE_BYTES (BN * BK * 2)                       // 65536
#define STAGE_BYTES   (A_STAGE_BYTES + B_STAGE_BYTES)     // 98304
#define GEMM_SMEM     (2 * STAGE_BYTES)                   // 196608

__device__ __forceinline__ uint32_t smem_u32(const void* p) {
    uint32_t a;
    asm("{ .reg .u64 t; cvta.to.shared.u64 t, %1; cvt.u32.u64 %0, t; }"
        : "=r"(a) : "l"(p));
    return a;
}
__device__ __forceinline__ void cp_async16(uint32_t saddr, const void* gptr) {
    asm volatile("cp.async.cg.shared.global [%0], [%1], 16;"
                 :: "r"(saddr), "l"(gptr));
}
#define CP_COMMIT() asm volatile("cp.async.commit_group;" ::: "memory")
#define CP_WAIT(n)  asm volatile("cp.async.wait_group %0;" :: "n"(n) : "memory")

__device__ __forceinline__ void ldmatrix_x4(uint32_t* r, uint32_t addr) {
    asm volatile("ldmatrix.sync.aligned.m8n8.x4.shared.b16 {%0,%1,%2,%3}, [%4];"
                 : "=r"(r[0]), "=r"(r[1]), "=r"(r[2]), "=r"(r[3]) : "r"(addr));
}
__device__ __forceinline__ void mma16816(float* c, const uint32_t* a,
                                         const uint32_t* b) {
    asm volatile("mma.sync.aligned.m16n8k16.row.col.f32.f16.f16.f32 "
                 "{%0,%1,%2,%3}, {%4,%5,%6,%7}, {%8,%9}, {%0,%1,%2,%3};"
                 : "+f"(c[0]), "+f"(c[1]), "+f"(c[2]), "+f"(c[3])
                 : "r"(a[0]), "r"(a[1]), "r"(a[2]), "r"(a[3]),
                   "r"(b[0]), "r"(b[1]));
}

__global__ __launch_bounds__(NTHREADS, 1) void gemm_mma_kernel(
    const float* __restrict__ bias, float* __restrict__ C)
{
    extern __shared__ char smem[];
    const uint32_t sbase = smem_u32(smem);
    const int tid  = threadIdx.x;
    const int wid  = tid >> 5;
    const int lane = tid & 31;
    const int cta  = blockIdx.x;
    const int warp_m = wid >> 3;
    const int warp_n = wid & 7;

    const int my_tiles = (NTILES - cta + GRID_P - 1) / GRID_P;
    const int total_it = my_tiles * ITERS_PT;

    auto load_stage = [&](int it) {
        const int tile = cta + (it >> 5) * GRID_P;
        const int bn   = tile & 15;
        const int bm   = tile >> 4;
        const int ko   = (it & 31) * BK;
        const __half* Ag = g_x_h + (size_t)(bm * BM) * IN_F + ko;
        const __half* Bg = g_w_h + (size_t)(bn * BN) * IN_F + ko;
        const uint32_t sA = sbase + (it & 1) * STAGE_BYTES;
        const uint32_t sB = sA + A_STAGE_BYTES;
        #pragma unroll
        for (int t = 0; t < 4; t++) {
            int v = tid + t * NTHREADS;
            int r = v >> 4, c = v & 15;
            uint32_t off = (uint32_t)(r << 8) + (uint32_t)((c ^ (r & 7)) << 4);
            cp_async16(sA + off, Ag + (size_t)r * IN_F + c * 8);
        }
        #pragma unroll
        for (int t = 0; t < 8; t++) {
            int v = tid + t * NTHREADS;
            int r = v >> 4, c = v & 15;
            uint32_t off = (uint32_t)(r << 8) + (uint32_t)((c ^ (r & 7)) << 4);
            cp_async16(sB + off, Bg + (size_t)r * IN_F + c * 8);
        }
    };

    const int m_lane  = warp_m * 64 + (lane & 15);
    const int a_half  = lane >> 4;
    const int xa      = m_lane & 7;
    const int n_lane  = warp_n * 32 + (lane & 7) + ((lane >> 4) << 3);
    const int b_half  = (lane >> 3) & 1;
    const int xb      = n_lane & 7;

    float acc[4][4][4];
    #pragma unroll
    for (int i = 0; i < 4; i++)
        #pragma unroll
        for (int j = 0; j < 4; j++)
            #pragma unroll
            for (int k = 0; k < 4; k++) acc[i][j][k] = 0.0f;

    if (total_it == 0) return;
    load_stage(0);
    CP_COMMIT();

    for (int it = 0; it < total_it; it++) {
        CP_WAIT(0);
        __syncthreads();

        if (it + 1 < total_it) load_stage(it + 1);
        CP_COMMIT();

        const uint32_t sA = sbase + (it & 1) * STAGE_BYTES;
        const uint32_t sB = sA + A_STAGE_BYTES;
        const uint32_t aRow = sA + (uint32_t)(m_lane << 8);
        const uint32_t bRow = sB + (uint32_t)(n_lane << 8);

        #pragma unroll
        for (int kk = 0; kk < 8; kk++) {
            uint32_t a_frag[4][4];
            uint32_t b_frag[2][4];
            const uint32_t ac = (uint32_t)(((kk * 2 + a_half) ^ xa) << 4);
            const uint32_t bc = (uint32_t)(((kk * 2 + b_half) ^ xb) << 4);
            #pragma unroll
            for (int mt = 0; mt < 4; mt++)
                ldmatrix_x4(a_frag[mt], aRow + (uint32_t)(mt << 12) + ac);
            #pragma unroll
            for (int nt = 0; nt < 2; nt++)
                ldmatrix_x4(b_frag[nt], bRow + (uint32_t)(nt << 12) + bc);
            #pragma unroll
            for (int mt = 0; mt < 4; mt++) {
                #pragma unroll
                for (int nt = 0; nt < 2; nt++) {
                    mma16816(acc[mt][2 * nt],     a_frag[mt], &b_frag[nt][0]);
                    mma16816(acc[mt][2 * nt + 1], a_frag[mt], &b_frag[nt][2]);
                }
            }
        }

        if ((it & 31) == 31) {
            const int tile = cta + (it >> 5) * GRID_P;
            const int bn   = tile & 15;
            const int bm   = tile >> 4;
            const int row_base = bm * BM + warp_m * 64 + (lane >> 2);
            const int col_base = bn * BN + warp_n * 32 + 2 * (lane & 3);
            #pragma unroll
            for (int mt = 0; mt < 4; mt++) {
                const int r0 = row_base + mt * 16;
                #pragma unroll
                for (int n8 = 0; n8 < 4; n8++) {
                    const int col = col_base + n8 * 8;
                    float2 bv = *reinterpret_cast<const float2*>(bias + col);
                    float2 o0, o1;
                    o0.x = acc[mt][n8][0] + bv.x;
                    o0.y = acc[mt][n8][1] + bv.y;
                    o1.x = acc[mt][n8][2] + bv.x;
                    o1.y = acc[mt][n8][3] + bv.y;
                    *reinterpret_cast<float2*>(
                        C + (size_t)r0 * OUT_F + col) = o0;
                    *reinterpret_cast<float2*>(
                        C + (size_t)(r0 + 8) * OUT_F + col) = o1;
                    #pragma unroll
                    for (int k = 0; k < 4; k++) acc[mt][n8][k] = 0.0f;
                }
            }
        }
    }
}

// ---------------------------------------------------------------------------
// Launch
// ---------------------------------------------------------------------------
extern "C" void kernel_launch(void* const* d_in, const int* in_sizes, int n_in,
                              void* d_out, int out_size)
{
    const float* x              = (const float*)d_in[0];
    const float* weight         = (const float*)d_in[1];
    const float* bias           = (const float*)d_in[2];
    const float* channel_scales = (const float*)d_in[3];
    const float* theta          = (const float*)d_in[4];
    const float* q_scale        = (const float*)d_in[5];
    const float* q_zp           = (const float*)d_in[6];
    const int*   pairs          = (const int*)d_in[7];
    float* out = (float*)d_out;

    cudaFuncSetAttribute(transform_kernel,
                         cudaFuncAttributeMaxDynamicSharedMemorySize, TSMEM_SZ);
    cudaFuncSetAttribute(gemm_mma_kernel,
                         cudaFuncAttributeMaxDynamicSharedMemorySize, GEMM_SMEM);

    dim3 tgrid(NGROUPS, OUT_F / ROWS_PB);
    transform_kernel<<<tgrid, 256, TSMEM_SZ>>>(weight, channel_scales, theta,
                                               q_scale, q_zp, pairs, x);

    gemm_mma_kernel<<<GRID_P, NTHREADS, GEMM_SMEM>>>(bias, out);
}

// round 16
// speedup vs baseline: 1.0294x; 1.0294x over previous
#include <cuda_runtime.h>
#include <cuda_fp16.h>
#include <cstdint>

#define IN_F     4096
#define OUT_F    4096
#define N_TOK    8192
#define GROUP    128
#define NGROUPS  (IN_F / GROUP)
#define N_STAGES 4
#define QMAXF    15.0f

// ---------------- scratch (device globals; no runtime allocation) ----------
__device__ __half g_w_h[(size_t)OUT_F * IN_F];
__device__ __half g_x_h[(size_t)N_TOK * IN_F];

// ---------------------------------------------------------------------------
// Kernel 1: fused weight transform + x->fp16 conversion.
// Transposed float2 tile wT2[channel][row_pair]: 64 rows/block as 32 pairs.
// Rotation LDS.64 is lane-consecutive -> conflict-free. ~39KB smem ->
// 5 CTAs/SM keeps DRAM streams latency-hidden. (R14, measured best.)
// ---------------------------------------------------------------------------
#define ROWS_PB 64
#define NPAIRS  (ROWS_PB / 2)                  // 32 row-pairs
#define RPAD    33
#define TBLOCKS (NGROUPS * (OUT_F / ROWS_PB))  // 2048
#define XCHUNK  ((size_t)N_TOK * IN_F / TBLOCKS)  // 16384 elems / block

__global__ __launch_bounds__(256) void transform_kernel(
    const float* __restrict__ weight,
    const float* __restrict__ channel_scales,
    const float* __restrict__ theta,
    const float* __restrict__ q_scale,
    const float* __restrict__ q_zp,
    const int*   __restrict__ pairs,
    const float* __restrict__ x)
{
    const int g    = blockIdx.x;               // 0..31
    const int row0 = blockIdx.y * ROWS_PB;     // 0..4032
    const int tid  = threadIdx.x;
    const int wrp  = tid >> 5;                 // 0..7
    const int lane = tid & 31;

    __shared__ float2 wT2[GROUP][RPAD];        // [channel][row_pair]
    __shared__ float cs_c[N_STAGES][64], cs_s[N_STAGES][64];
    __shared__ int   pi[N_STAGES][64], pj[N_STAGES][64];
    __shared__ float csc[GROUP];
    __shared__ float qs[ROWS_PB], qz[ROWS_PB];

    // ---- fused x -> fp16 conversion (independent DRAM stream) ----
    {
        const int blk = blockIdx.y * NGROUPS + blockIdx.x;   // 0..2047
        const float* xs = x + (size_t)blk * XCHUNK;
        __half* xd = g_x_h + (size_t)blk * XCHUNK;
        #pragma unroll
        for (int t = 0; t < (int)(XCHUNK / (256 * 8)); t++) {  // 8 iters
            size_t i = ((size_t)(t * 256 + tid)) * 8;
            float4 v0 = *reinterpret_cast<const float4*>(xs + i);
            float4 v1 = *reinterpret_cast<const float4*>(xs + i + 4);
            __half2 h[4];
            h[0] = __floats2half2_rn(v0.x, v0.y);
            h[1] = __floats2half2_rn(v0.z, v0.w);
            h[2] = __floats2half2_rn(v1.x, v1.y);
            h[3] = __floats2half2_rn(v1.z, v1.w);
            *reinterpret_cast<uint4*>(xd + i) =
                *reinterpret_cast<const uint4*>(h);
        }
    }

    // ---- tables ----
    if (tid < GROUP) csc[tid] = channel_scales[g * GROUP + tid];
    {
        int st = tid >> 6, p = tid & 63;       // 256 = 4 stages x 64 pairs
        float s, c;
        sincosf(theta[st * (IN_F / 2) + g * 64 + p], &s, &c);
        cs_c[st][p] = c;
        cs_s[st][p] = s;
        pi[st][p] = pairs[st * IN_F + g * GROUP + 2 * p];
        pj[st][p] = pairs[st * IN_F + g * GROUP + 2 * p + 1];
    }
    if (tid < ROWS_PB) {
        int gi = (row0 + tid) * NGROUPS + g;
        qs[tid] = fminf(fmaxf(q_scale[gi], 1e-5f), 1e5f);
        qz[tid] = fminf(fmaxf(-rintf(q_zp[gi]), 0.0f), QMAXF);
    }
    __syncthreads();

    // ---- transposed load + channel scale (two rows per float2) ----
    const int lr2 = wrp * 4 + (lane >> 3);     // row-pair index 0..31
    const int rowa = row0 + 2 * lr2;
    #pragma unroll
    for (int it = 0; it < 4; it++) {
        int c4 = ((lane & 7) + it * 8) * 4;
        float4 va = *reinterpret_cast<const float4*>(
            weight + (size_t)rowa * IN_F + g * GROUP + c4);
        float4 vb = *reinterpret_cast<const float4*>(
            weight + (size_t)(rowa + 1) * IN_F + g * GROUP + c4);
        wT2[c4 + 0][lr2] = make_float2(va.x * csc[c4 + 0], vb.x * csc[c4 + 0]);
        wT2[c4 + 1][lr2] = make_float2(va.y * csc[c4 + 1], vb.y * csc[c4 + 1]);
        wT2[c4 + 2][lr2] = make_float2(va.z * csc[c4 + 2], vb.z * csc[c4 + 2]);
        wT2[c4 + 3][lr2] = make_float2(va.w * csc[c4 + 3], vb.w * csc[c4 + 3]);
    }
    __syncthreads();

    // ---- forward rotations: lane = row-pair, conflict-free LDS.64 ----
    #pragma unroll
    for (int st = 0; st < N_STAGES; st++) {
        #pragma unroll
        for (int t = 0; t < 8; t++) {
            int p = wrp + t * 8;
            float c = cs_c[st][p], s = cs_s[st][p];
            int i = pi[st][p], j = pj[st][p];
            float2 xi = wT2[i][lane], xj = wT2[j][lane];
            wT2[i][lane] = make_float2( xi.x * c + xj.x * s,
                                        xi.y * c + xj.y * s);
            wT2[j][lane] = make_float2(-xi.x * s + xj.x * c,
                                       -xi.y * s + xj.y * c);
        }
        __syncthreads();
    }

    // ---- quant-dequant: lane owns rows (2*lane, 2*lane+1) ----
    {
        float sa = qs[2 * lane],     za = qz[2 * lane];
        float sb = qs[2 * lane + 1], zb = qz[2 * lane + 1];
        #pragma unroll
        for (int t = 0; t < 16; t++) {
            int c = wrp + t * 8;
            float2 v = wT2[c][lane];
            float qa = rintf(v.x / sa) + za;
            qa = fminf(fmaxf(qa, 0.0f), QMAXF);
            float qb = rintf(v.y / sb) + zb;
            qb = fminf(fmaxf(qb, 0.0f), QMAXF);
            wT2[c][lane] = make_float2((qa - za) * sa, (qb - zb) * sb);
        }
    }
    __syncthreads();

    // ---- inverse rotations ----
    #pragma unroll
    for (int st = N_STAGES - 1; st >= 0; st--) {
        #pragma unroll
        for (int t = 0; t < 8; t++) {
            int p = wrp + t * 8;
            float c = cs_c[st][p], s = cs_s[st][p];
            int i = pi[st][p], j = pj[st][p];
            float2 xi = wT2[i][lane], xj = wT2[j][lane];
            wT2[i][lane] = make_float2(xi.x * c - xj.x * s,
                                       xi.y * c - xj.y * s);
            wT2[j][lane] = make_float2(xi.x * s + xj.x * c,
                                       xi.y * s + xj.y * c);
        }
        __syncthreads();
    }

    // ---- unscale + fp16 store (8B stores, both rows) ----
    #pragma unroll
    for (int it = 0; it < 4; it++) {
        int c4 = ((lane & 7) + it * 8) * 4;
        float2 u0 = wT2[c4 + 0][lr2];
        float2 u1 = wT2[c4 + 1][lr2];
        float2 u2 = wT2[c4 + 2][lr2];
        float2 u3 = wT2[c4 + 3][lr2];
        float i0 = csc[c4 + 0], i1 = csc[c4 + 1];
        float i2 = csc[c4 + 2], i3 = csc[c4 + 3];
        __half2 ha[2], hb[2];
        ha[0] = __floats2half2_rn(u0.x / i0, u1.x / i1);
        ha[1] = __floats2half2_rn(u2.x / i2, u3.x / i3);
        hb[0] = __floats2half2_rn(u0.y / i0, u1.y / i1);
        hb[1] = __floats2half2_rn(u2.y / i2, u3.y / i3);
        *reinterpret_cast<uint2*>(
            g_w_h + (size_t)rowa * IN_F + g * GROUP + c4) =
            *reinterpret_cast<const uint2*>(ha);
        *reinterpret_cast<uint2*>(
            g_w_h + (size_t)(rowa + 1) * IN_F + g * GROUP + c4) =
            *reinterpret_cast<const uint2*>(hb);
    }
}

// ---------------------------------------------------------------------------
// Kernel 2: PERSISTENT fp16 mma.sync GEMM (measured ~615-620us; parked).
// CTA 128x256, 512 threads, warp tile 64x32, BK=128, 2-stage, grid=148.
// ---------------------------------------------------------------------------
#define BM 128
#define BN 256
#define BK 128
#define NTHREADS 512
#define GRID_P   148
#define NTILES   ((OUT_F / BN) * (N_TOK / BM))            // 1024
#define ITERS_PT (IN_F / BK)                              // 32
#define A_STAGE_BYTES (BM * BK * 2)                       // 32768
#define B_STAGE_BYTES (BN * BK * 2)                       // 65536
#define STAGE_BYTES   (A_STAGE_BYTES + B_STAGE_BYTES)     // 98304
#define GEMM_SMEM     (2 * STAGE_BYTES)                   // 196608

__device__ __forceinline__ uint32_t smem_u32(const void* p) {
    uint32_t a;
    asm("{ .reg .u64 t; cvta.to.shared.u64 t, %1; cvt.u32.u64 %0, t; }"
        : "=r"(a) : "l"(p));
    return a;
}
__device__ __forceinline__ void cp_async16(uint32_t saddr, const void* gptr) {
    asm volatile("cp.async.cg.shared.global [%0], [%1], 16;"
                 :: "r"(saddr), "l"(gptr));
}
#define CP_COMMIT() asm volatile("cp.async.commit_group;" ::: "memory")
#define CP_WAIT(n)  asm volatile("cp.async.wait_group %0;" :: "n"(n) : "memory")

__device__ __forceinline__ void ldmatrix_x4(uint32_t* r, uint32_t addr) {
    asm volatile("ldmatrix.sync.aligned.m8n8.x4.shared.b16 {%0,%1,%2,%3}, [%4];"
                 : "=r"(r[0]), "=r"(r[1]), "=r"(r[2]), "=r"(r[3]) : "r"(addr));
}
__device__ __forceinline__ void mma16816(float* c, const uint32_t* a,
                                         const uint32_t* b) {
    asm volatile("mma.sync.aligned.m16n8k16.row.col.f32.f16.f16.f32 "
                 "{%0,%1,%2,%3}, {%4,%5,%6,%7}, {%8,%9}, {%0,%1,%2,%3};"
                 : "+f"(c[0]), "+f"(c[1]), "+f"(c[2]), "+f"(c[3])
                 : "r"(a[0]), "r"(a[1]), "r"(a[2]), "r"(a[3]),
                   "r"(b[0]), "r"(b[1]));
}

__global__ __launch_bounds__(NTHREADS, 1) void gemm_mma_kernel(
    const float* __restrict__ bias, float* __restrict__ C)
{
    extern __shared__ char smem[];
    const uint32_t sbase = smem_u32(smem);
    const int tid  = threadIdx.x;
    const int wid  = tid >> 5;
    const int lane = tid & 31;
    const int cta  = blockIdx.x;
    const int warp_m = wid >> 3;
    const int warp_n = wid & 7;

    const int my_tiles = (NTILES - cta + GRID_P - 1) / GRID_P;
    const int total_it = my_tiles * ITERS_PT;

    auto load_stage = [&](int it) {
        const int tile = cta + (it >> 5) * GRID_P;
        const int bn   = tile & 15;
        const int bm   = tile >> 4;
        const int ko   = (it & 31) * BK;
        const __half* Ag = g_x_h + (size_t)(bm * BM) * IN_F + ko;
        const __half* Bg = g_w_h + (size_t)(bn * BN) * IN_F + ko;
        const uint32_t sA = sbase + (it & 1) * STAGE_BYTES;
        const uint32_t sB = sA + A_STAGE_BYTES;
        #pragma unroll
        for (int t = 0; t < 4; t++) {
            int v = tid + t * NTHREADS;
            int r = v >> 4, c = v & 15;
            uint32_t off = (uint32_t)(r << 8) + (uint32_t)((c ^ (r & 7)) << 4);
            cp_async16(sA + off, Ag + (size_t)r * IN_F + c * 8);
        }
        #pragma unroll
        for (int t = 0; t < 8; t++) {
            int v = tid + t * NTHREADS;
            int r = v >> 4, c = v & 15;
            uint32_t off = (uint32_t)(r << 8) + (uint32_t)((c ^ (r & 7)) << 4);
            cp_async16(sB + off, Bg + (size_t)r * IN_F + c * 8);
        }
    };

    const int m_lane  = warp_m * 64 + (lane & 15);
    const int a_half  = lane >> 4;
    const int xa      = m_lane & 7;
    const int n_lane  = warp_n * 32 + (lane & 7) + ((lane >> 4) << 3);
    const int b_half  = (lane >> 3) & 1;
    const int xb      = n_lane & 7;

    float acc[4][4][4];
    #pragma unroll
    for (int i = 0; i < 4; i++)
        #pragma unroll
        for (int j = 0; j < 4; j++)
            #pragma unroll
            for (int k = 0; k < 4; k++) acc[i][j][k] = 0.0f;

    if (total_it == 0) return;
    load_stage(0);
    CP_COMMIT();

    for (int it = 0; it < total_it; it++) {
        CP_WAIT(0);
        __syncthreads();

        if (it + 1 < total_it) load_stage(it + 1);
        CP_COMMIT();

        const uint32_t sA = sbase + (it & 1) * STAGE_BYTES;
        const uint32_t sB = sA + A_STAGE_BYTES;
        const uint32_t aRow = sA + (uint32_t)(m_lane << 8);
        const uint32_t bRow = sB + (uint32_t)(n_lane << 8);

        #pragma unroll
        for (int kk = 0; kk < 8; kk++) {
            uint32_t a_frag[4][4];
            uint32_t b_frag[2][4];
            const uint32_t ac = (uint32_t)(((kk * 2 + a_half) ^ xa) << 4);
            const uint32_t bc = (uint32_t)(((kk * 2 + b_half) ^ xb) << 4);
            #pragma unroll
            for (int mt = 0; mt < 4; mt++)
                ldmatrix_x4(a_frag[mt], aRow + (uint32_t)(mt << 12) + ac);
            #pragma unroll
            for (int nt = 0; nt < 2; nt++)
                ldmatrix_x4(b_frag[nt], bRow + (uint32_t)(nt << 12) + bc);
            #pragma unroll
            for (int mt = 0; mt < 4; mt++) {
                #pragma unroll
                for (int nt = 0; nt < 2; nt++) {
                    mma16816(acc[mt][2 * nt],     a_frag[mt], &b_frag[nt][0]);
                    mma16816(acc[mt][2 * nt + 1], a_frag[mt], &b_frag[nt][2]);
                }
            }
        }

        if ((it & 31) == 31) {
            const int tile = cta + (it >> 5) * GRID_P;
            const int bn   = tile & 15;
            const int bm   = tile >> 4;
            const int row_base = bm * BM + warp_m * 64 + (lane >> 2);
            const int col_base = bn * BN + warp_n * 32 + 2 * (lane & 3);
            #pragma unroll
            for (int mt = 0; mt < 4; mt++) {
                const int r0 = row_base + mt * 16;
                #pragma unroll
                for (int n8 = 0; n8 < 4; n8++) {
                    const int col = col_base + n8 * 8;
                    float2 bv = *reinterpret_cast<const float2*>(bias + col);
                    float2 o0, o1;
                    o0.x = acc[mt][n8][0] + bv.x;
                    o0.y = acc[mt][n8][1] + bv.y;
                    o1.x = acc[mt][n8][2] + bv.x;
                    o1.y = acc[mt][n8][3] + bv.y;
                    *reinterpret_cast<float2*>(
                        C + (size_t)r0 * OUT_F + col) = o0;
                    *reinterpret_cast<float2*>(
                        C + (size_t)(r0 + 8) * OUT_F + col) = o1;
                    #pragma unroll
                    for (int k = 0; k < 4; k++) acc[mt][n8][k] = 0.0f;
                }
            }
        }
    }
}

// ---------------------------------------------------------------------------
// Launch
// ---------------------------------------------------------------------------
extern "C" void kernel_launch(void* const* d_in, const int* in_sizes, int n_in,
                              void* d_out, int out_size)
{
    const float* x              = (const float*)d_in[0];
    const float* weight         = (const float*)d_in[1];
    const float* bias           = (const float*)d_in[2];
    const float* channel_scales = (const float*)d_in[3];
    const float* theta          = (const float*)d_in[4];
    const float* q_scale        = (const float*)d_in[5];
    const float* q_zp           = (const float*)d_in[6];
    const int*   pairs          = (const int*)d_in[7];
    float* out = (float*)d_out;

    cudaFuncSetAttribute(gemm_mma_kernel,
                         cudaFuncAttributeMaxDynamicSharedMemorySize, GEMM_SMEM);

    dim3 tgrid(NGROUPS, OUT_F / ROWS_PB);
    transform_kernel<<<tgrid, 256>>>(weight, channel_scales, theta,
                                     q_scale, q_zp, pairs, x);

    gemm_mma_kernel<<<GRID_P, NTHREADS, GEMM_SMEM>>>(bias, out);
}

// round 17
// speedup vs baseline: 1.0467x; 1.0169x over previous
#include <cuda_runtime.h>
#include <cuda_fp16.h>
#include <cstdint>

#define IN_F     4096
#define OUT_F    4096
#define N_TOK    8192
#define GROUP    128
#define NGROUPS  (IN_F / GROUP)
#define N_STAGES 4
#define QMAXF    15.0f

// ---------------- scratch (device globals; no runtime allocation) ----------
__device__ __half g_w_h[(size_t)OUT_F * IN_F];
__device__ __half g_x_h[(size_t)N_TOK * IN_F];

// ---------------------------------------------------------------------------
// Kernel 1: fused weight transform + x->fp16 conversion (R14, measured best).
// Transposed float2 tile wT2[channel][row_pair], conflict-free LDS.64.
// ---------------------------------------------------------------------------
#define ROWS_PB 64
#define RPAD    33
#define TBLOCKS (NGROUPS * (OUT_F / ROWS_PB))  // 2048
#define XCHUNK  ((size_t)N_TOK * IN_F / TBLOCKS)  // 16384 elems / block

__global__ __launch_bounds__(256) void transform_kernel(
    const float* __restrict__ weight,
    const float* __restrict__ channel_scales,
    const float* __restrict__ theta,
    const float* __restrict__ q_scale,
    const float* __restrict__ q_zp,
    const int*   __restrict__ pairs,
    const float* __restrict__ x)
{
    const int g    = blockIdx.x;
    const int row0 = blockIdx.y * ROWS_PB;
    const int tid  = threadIdx.x;
    const int wrp  = tid >> 5;
    const int lane = tid & 31;

    __shared__ float2 wT2[GROUP][RPAD];
    __shared__ float cs_c[N_STAGES][64], cs_s[N_STAGES][64];
    __shared__ int   pi[N_STAGES][64], pj[N_STAGES][64];
    __shared__ float csc[GROUP];
    __shared__ float qs[ROWS_PB], qz[ROWS_PB];

    // ---- fused x -> fp16 conversion ----
    {
        const int blk = blockIdx.y * NGROUPS + blockIdx.x;
        const float* xs = x + (size_t)blk * XCHUNK;
        __half* xd = g_x_h + (size_t)blk * XCHUNK;
        #pragma unroll
        for (int t = 0; t < (int)(XCHUNK / (256 * 8)); t++) {
            size_t i = ((size_t)(t * 256 + tid)) * 8;
            float4 v0 = *reinterpret_cast<const float4*>(xs + i);
            float4 v1 = *reinterpret_cast<const float4*>(xs + i + 4);
            __half2 h[4];
            h[0] = __floats2half2_rn(v0.x, v0.y);
            h[1] = __floats2half2_rn(v0.z, v0.w);
            h[2] = __floats2half2_rn(v1.x, v1.y);
            h[3] = __floats2half2_rn(v1.z, v1.w);
            *reinterpret_cast<uint4*>(xd + i) =
                *reinterpret_cast<const uint4*>(h);
        }
    }

    // ---- tables ----
    if (tid < GROUP) csc[tid] = channel_scales[g * GROUP + tid];
    {
        int st = tid >> 6, p = tid & 63;
        float s, c;
        sincosf(theta[st * (IN_F / 2) + g * 64 + p], &s, &c);
        cs_c[st][p] = c;
        cs_s[st][p] = s;
        pi[st][p] = pairs[st * IN_F + g * GROUP + 2 * p];
        pj[st][p] = pairs[st * IN_F + g * GROUP + 2 * p + 1];
    }
    if (tid < ROWS_PB) {
        int gi = (row0 + tid) * NGROUPS + g;
        qs[tid] = fminf(fmaxf(q_scale[gi], 1e-5f), 1e5f);
        qz[tid] = fminf(fmaxf(-rintf(q_zp[gi]), 0.0f), QMAXF);
    }
    __syncthreads();

    // ---- transposed load + channel scale ----
    const int lr2 = wrp * 4 + (lane >> 3);
    const int rowa = row0 + 2 * lr2;
    #pragma unroll
    for (int it = 0; it < 4; it++) {
        int c4 = ((lane & 7) + it * 8) * 4;
        float4 va = *reinterpret_cast<const float4*>(
            weight + (size_t)rowa * IN_F + g * GROUP + c4);
        float4 vb = *reinterpret_cast<const float4*>(
            weight + (size_t)(rowa + 1) * IN_F + g * GROUP + c4);
        wT2[c4 + 0][lr2] = make_float2(va.x * csc[c4 + 0], vb.x * csc[c4 + 0]);
        wT2[c4 + 1][lr2] = make_float2(va.y * csc[c4 + 1], vb.y * csc[c4 + 1]);
        wT2[c4 + 2][lr2] = make_float2(va.z * csc[c4 + 2], vb.z * csc[c4 + 2]);
        wT2[c4 + 3][lr2] = make_float2(va.w * csc[c4 + 3], vb.w * csc[c4 + 3]);
    }
    __syncthreads();

    // ---- forward rotations ----
    #pragma unroll
    for (int st = 0; st < N_STAGES; st++) {
        #pragma unroll
        for (int t = 0; t < 8; t++) {
            int p = wrp + t * 8;
            float c = cs_c[st][p], s = cs_s[st][p];
            int i = pi[st][p], j = pj[st][p];
            float2 xi = wT2[i][lane], xj = wT2[j][lane];
            wT2[i][lane] = make_float2( xi.x * c + xj.x * s,
                                        xi.y * c + xj.y * s);
            wT2[j][lane] = make_float2(-xi.x * s + xj.x * c,
                                       -xi.y * s + xj.y * c);
        }
        __syncthreads();
    }

    // ---- quant-dequant ----
    {
        float sa = qs[2 * lane],     za = qz[2 * lane];
        float sb = qs[2 * lane + 1], zb = qz[2 * lane + 1];
        #pragma unroll
        for (int t = 0; t < 16; t++) {
            int c = wrp + t * 8;
            float2 v = wT2[c][lane];
            float qa = rintf(v.x / sa) + za;
            qa = fminf(fmaxf(qa, 0.0f), QMAXF);
            float qb = rintf(v.y / sb) + zb;
            qb = fminf(fmaxf(qb, 0.0f), QMAXF);
            wT2[c][lane] = make_float2((qa - za) * sa, (qb - zb) * sb);
        }
    }
    __syncthreads();

    // ---- inverse rotations ----
    #pragma unroll
    for (int st = N_STAGES - 1; st >= 0; st--) {
        #pragma unroll
        for (int t = 0; t < 8; t++) {
            int p = wrp + t * 8;
            float c = cs_c[st][p], s = cs_s[st][p];
            int i = pi[st][p], j = pj[st][p];
            float2 xi = wT2[i][lane], xj = wT2[j][lane];
            wT2[i][lane] = make_float2(xi.x * c - xj.x * s,
                                       xi.y * c - xj.y * s);
            wT2[j][lane] = make_float2(xi.x * s + xj.x * c,
                                       xi.y * s + xj.y * c);
        }
        __syncthreads();
    }

    // ---- unscale + fp16 store ----
    #pragma unroll
    for (int it = 0; it < 4; it++) {
        int c4 = ((lane & 7) + it * 8) * 4;
        float2 u0 = wT2[c4 + 0][lr2];
        float2 u1 = wT2[c4 + 1][lr2];
        float2 u2 = wT2[c4 + 2][lr2];
        float2 u3 = wT2[c4 + 3][lr2];
        float i0 = csc[c4 + 0], i1 = csc[c4 + 1];
        float i2 = csc[c4 + 2], i3 = csc[c4 + 3];
        __half2 ha[2], hb[2];
        ha[0] = __floats2half2_rn(u0.x / i0, u1.x / i1);
        ha[1] = __floats2half2_rn(u2.x / i2, u3.x / i3);
        hb[0] = __floats2half2_rn(u0.y / i0, u1.y / i1);
        hb[1] = __floats2half2_rn(u2.y / i2, u3.y / i3);
        *reinterpret_cast<uint2*>(
            g_w_h + (size_t)rowa * IN_F + g * GROUP + c4) =
            *reinterpret_cast<const uint2*>(ha);
        *reinterpret_cast<uint2*>(
            g_w_h + (size_t)(rowa + 1) * IN_F + g * GROUP + c4) =
            *reinterpret_cast<const uint2*>(hb);
    }
}

// ---------------------------------------------------------------------------
// Kernel 2: PERSISTENT fp16 mma.sync GEMM. CTA 128x256, 256 threads (8 warps),
// warp tile 64x64 (1.5x less LDSM per MMA), BK=128 2-stage, grid=148.
// ---------------------------------------------------------------------------
#define BM 128
#define BN 256
#define BK 128
#define NTHREADS 256
#define GRID_P   148
#define NTILES   ((OUT_F / BN) * (N_TOK / BM))            // 1024
#define ITERS_PT (IN_F / BK)                              // 32
#define A_STAGE_BYTES (BM * BK * 2)                       // 32768
#define B_STAGE_BYTES (BN * BK * 2)                       // 65536
#define STAGE_BYTES   (A_STAGE_BYTES + B_STAGE_BYTES)     // 98304
#define GEMM_SMEM     (2 * STAGE_BYTES)                   // 196608

__device__ __forceinline__ uint32_t smem_u32(const void* p) {
    uint32_t a;
    asm("{ .reg .u64 t; cvta.to.shared.u64 t, %1; cvt.u32.u64 %0, t; }"
        : "=r"(a) : "l"(p));
    return a;
}
__device__ __forceinline__ void cp_async16(uint32_t saddr, const void* gptr) {
    asm volatile("cp.async.cg.shared.global [%0], [%1], 16;"
                 :: "r"(saddr), "l"(gptr));
}
#define CP_COMMIT() asm volatile("cp.async.commit_group;" ::: "memory")
#define CP_WAIT(n)  asm volatile("cp.async.wait_group %0;" :: "n"(n) : "memory")

__device__ __forceinline__ void ldmatrix_x4(uint32_t* r, uint32_t addr) {
    asm volatile("ldmatrix.sync.aligned.m8n8.x4.shared.b16 {%0,%1,%2,%3}, [%4];"
                 : "=r"(r[0]), "=r"(r[1]), "=r"(r[2]), "=r"(r[3]) : "r"(addr));
}
__device__ __forceinline__ void mma16816(float* c, const uint32_t* a,
                                         const uint32_t* b) {
    asm volatile("mma.sync.aligned.m16n8k16.row.col.f32.f16.f16.f32 "
                 "{%0,%1,%2,%3}, {%4,%5,%6,%7}, {%8,%9}, {%0,%1,%2,%3};"
                 : "+f"(c[0]), "+f"(c[1]), "+f"(c[2]), "+f"(c[3])
                 : "r"(a[0]), "r"(a[1]), "r"(a[2]), "r"(a[3]),
                   "r"(b[0]), "r"(b[1]));
}

__global__ __launch_bounds__(NTHREADS, 1) void gemm_mma_kernel(
    const float* __restrict__ bias, float* __restrict__ C)
{
    extern __shared__ char smem[];
    const uint32_t sbase = smem_u32(smem);
    const int tid  = threadIdx.x;
    const int wid  = tid >> 5;
    const int lane = tid & 31;
    const int cta  = blockIdx.x;
    const int warp_m = wid >> 2;         // 0..1 -> 64 rows
    const int warp_n = wid & 3;          // 0..3 -> 64 cols

    const int my_tiles = (NTILES - cta + GRID_P - 1) / GRID_P;
    const int total_it = my_tiles * ITERS_PT;

    auto load_stage = [&](int it) {
        const int tile = cta + (it >> 5) * GRID_P;
        const int bn   = tile & 15;
        const int bm   = tile >> 4;
        const int ko   = (it & 31) * BK;
        const __half* Ag = g_x_h + (size_t)(bm * BM) * IN_F + ko;
        const __half* Bg = g_w_h + (size_t)(bn * BN) * IN_F + ko;
        const uint32_t sA = sbase + (it & 1) * STAGE_BYTES;
        const uint32_t sB = sA + A_STAGE_BYTES;
        #pragma unroll
        for (int t = 0; t < 8; t++) {        // A: 2048 chunks / 256 thr
            int v = tid + t * NTHREADS;
            int r = v >> 4, c = v & 15;
            uint32_t off = (uint32_t)(r << 8) + (uint32_t)((c ^ (r & 7)) << 4);
            cp_async16(sA + off, Ag + (size_t)r * IN_F + c * 8);
        }
        #pragma unroll
        for (int t = 0; t < 16; t++) {       // B: 4096 chunks / 256 thr
            int v = tid + t * NTHREADS;
            int r = v >> 4, c = v & 15;
            uint32_t off = (uint32_t)(r << 8) + (uint32_t)((c ^ (r & 7)) << 4);
            cp_async16(sB + off, Bg + (size_t)r * IN_F + c * 8);
        }
    };

    const int m_lane  = warp_m * 64 + (lane & 15);
    const int a_half  = lane >> 4;
    const int xa      = m_lane & 7;
    const int n_lane  = warp_n * 64 + (lane & 7) + ((lane >> 4) << 3);
    const int b_half  = (lane >> 3) & 1;
    const int xb      = n_lane & 7;

    float acc[4][8][4];
    #pragma unroll
    for (int i = 0; i < 4; i++)
        #pragma unroll
        for (int j = 0; j < 8; j++)
            #pragma unroll
            for (int k = 0; k < 4; k++) acc[i][j][k] = 0.0f;

    if (total_it == 0) return;
    load_stage(0);
    CP_COMMIT();

    for (int it = 0; it < total_it; it++) {
        CP_WAIT(0);
        __syncthreads();

        if (it + 1 < total_it) load_stage(it + 1);
        CP_COMMIT();

        const uint32_t sA = sbase + (it & 1) * STAGE_BYTES;
        const uint32_t sB = sA + A_STAGE_BYTES;
        const uint32_t aRow = sA + (uint32_t)(m_lane << 8);
        const uint32_t bRow = sB + (uint32_t)(n_lane << 8);

        #pragma unroll
        for (int kk = 0; kk < 8; kk++) {
            uint32_t a_frag[4][4];
            uint32_t b_frag[4][4];
            const uint32_t ac = (uint32_t)(((kk * 2 + a_half) ^ xa) << 4);
            const uint32_t bc = (uint32_t)(((kk * 2 + b_half) ^ xb) << 4);
            #pragma unroll
            for (int mt = 0; mt < 4; mt++)
                ldmatrix_x4(a_frag[mt], aRow + (uint32_t)(mt << 12) + ac);
            #pragma unroll
            for (int nt = 0; nt < 4; nt++)
                ldmatrix_x4(b_frag[nt], bRow + (uint32_t)(nt << 12) + bc);
            #pragma unroll
            for (int mt = 0; mt < 4; mt++) {
                #pragma unroll
                for (int nt = 0; nt < 4; nt++) {
                    mma16816(acc[mt][2 * nt],     a_frag[mt], &b_frag[nt][0]);
                    mma16816(acc[mt][2 * nt + 1], a_frag[mt], &b_frag[nt][2]);
                }
            }
        }

        if ((it & 31) == 31) {
            const int tile = cta + (it >> 5) * GRID_P;
            const int bn   = tile & 15;
            const int bm   = tile >> 4;
            const int row_base = bm * BM + warp_m * 64 + (lane >> 2);
            const int col_base = bn * BN + warp_n * 64 + 2 * (lane & 3);
            #pragma unroll
            for (int mt = 0; mt < 4; mt++) {
                const int r0 = row_base + mt * 16;
                #pragma unroll
                for (int n8 = 0; n8 < 8; n8++) {
                    const int col = col_base + n8 * 8;
                    float2 bv = *reinterpret_cast<const float2*>(bias + col);
                    float2 o0, o1;
                    o0.x = acc[mt][n8][0] + bv.x;
                    o0.y = acc[mt][n8][1] + bv.y;
                    o1.x = acc[mt][n8][2] + bv.x;
                    o1.y = acc[mt][n8][3] + bv.y;
                    *reinterpret_cast<float2*>(
                        C + (size_t)r0 * OUT_F + col) = o0;
                    *reinterpret_cast<float2*>(
                        C + (size_t)(r0 + 8) * OUT_F + col) = o1;
                    #pragma unroll
                    for (int k = 0; k < 4; k++) acc[mt][n8][k] = 0.0f;
                }
            }
        }
    }
}

// ---------------------------------------------------------------------------
// Launch
// ---------------------------------------------------------------------------
extern "C" void kernel_launch(void* const* d_in, const int* in_sizes, int n_in,
                              void* d_out, int out_size)
{
    const float* x              = (const float*)d_in[0];
    const float* weight         = (const float*)d_in[1];
    const float* bias           = (const float*)d_in[2];
    const float* channel_scales = (const float*)d_in[3];
    const float* theta          = (const float*)d_in[4];
    const float* q_scale        = (const float*)d_in[5];
    const float* q_zp           = (const float*)d_in[6];
    const int*   pairs          = (const int*)d_in[7];
    float* out = (float*)d_out;

    cudaFuncSetAttribute(gemm_mma_kernel,
                         cudaFuncAttributeMaxDynamicSharedMemorySize, GEMM_SMEM);

    dim3 tgrid(NGROUPS, OUT_F / ROWS_PB);
    transform_kernel<<<tgrid, 256>>>(weight, channel_scales, theta,
                                     q_scale, q_zp, pairs, x);

    gemm_mma_kernel<<<GRID_P, NTHREADS, GEMM_SMEM>>>(bias, out);
}